// round 10
// baseline (speedup 1.0000x reference)
#include <cuda_runtime.h>
#include <cuda_bf16.h>
#include <math.h>

// Problem constants
#define B_   16
#define T_   512
#define C_   8
#define S_   64
#define KSZ_ 32
#define TOUT_ 481   // T - KSZ + 1

// Scratch (no allocations allowed in kernel_launch)
__device__ float g_xmean[B_ * C_];
__device__ float g_xrstd[B_ * C_];
// Packed kernel constants, per k (KSZ index):
//   g_kq[k*512 + sp*16 + i*2 + half] = -2 * kern_norm[s = 2*sp + half][k][i]
__device__ __align__(16) float g_kq[KSZ_ * 32 * 16];   // 16384 floats
//   g_kc[k*64 + sp*2 + half] = sum_c kern_norm[s][k][c]^2
__device__ __align__(16) float g_kc[KSZ_ * S_];        // 2048 floats

// ---------------------------------------------------------------------------
__device__ __forceinline__ void warp_red2(float& a, float& b) {
    #pragma unroll
    for (int o = 16; o > 0; o >>= 1) {
        a += __shfl_xor_sync(0xffffffffu, a, o);
        b += __shfl_xor_sync(0xffffffffu, b, o);
    }
}

// ---------------------------------------------------------------------------
// Kernel 1: stats + kernel normalization/reorder. Triggers PDL at end.
// ---------------------------------------------------------------------------
__global__ void lsd_stats_kernel(const float* __restrict__ x,
                                 const float* __restrict__ kern) {
    __shared__ float r1[8];
    __shared__ float r2[8];
    __shared__ float s_mean, s_rstd;
    int tid = threadIdx.x;
    int wid = tid >> 5;
    int lid = tid & 31;

    if (blockIdx.x < 128) {
        int b = blockIdx.x >> 3;
        int c = blockIdx.x & 7;
        const float* xp = x + (size_t)b * T_ * C_ + c;
        float v0 = xp[(size_t)tid * C_];
        float v1 = xp[(size_t)(tid + 256) * C_];
        float sum = v0 + v1;
        float sq  = v0 * v0 + v1 * v1;
        warp_red2(sum, sq);
        if (lid == 0) { r1[wid] = sum; r2[wid] = sq; }
        __syncthreads();
        if (wid == 0) {
            float a = (lid < 8) ? r1[lid] : 0.0f;
            float bq = (lid < 8) ? r2[lid] : 0.0f;
            #pragma unroll
            for (int o = 4; o > 0; o >>= 1) {
                a  += __shfl_xor_sync(0xffffffffu, a, o);
                bq += __shfl_xor_sync(0xffffffffu, bq, o);
            }
            if (lid == 0) {
                float mean = a * (1.0f / T_);
                float var  = bq * (1.0f / T_) - mean * mean;
                float std  = sqrtf(fmaxf(var, 0.0f)) + 1e-8f;
                g_xmean[b * C_ + c] = mean;
                g_xrstd[b * C_ + c] = 1.0f / std;
            }
        }
    } else {
        int s = blockIdx.x - 128;
        const float* kp = kern + (size_t)s * KSZ_ * C_;
        float v = kp[tid];
        float sum = v, sq = v * v;
        warp_red2(sum, sq);
        if (lid == 0) { r1[wid] = sum; r2[wid] = sq; }
        __syncthreads();
        if (tid == 0) {
            float a = 0.0f, bq = 0.0f;
            #pragma unroll
            for (int j = 0; j < 8; j++) { a += r1[j]; bq += r2[j]; }
            float mean = a * (1.0f / 256.0f);
            float var  = bq * (1.0f / 256.0f) - mean * mean;
            float std  = sqrtf(fmaxf(var, 0.0f)) + 1e-8f;
            s_mean = mean;
            s_rstd = 1.0f / std;
        }
        __syncthreads();

        float norm = (v - s_mean) * s_rstd;
        int k = tid >> 3;
        int c = tid & 7;
        int sp = s >> 1;
        int half = s & 1;
        g_kq[k * 512 + sp * 16 + c * 2 + half] = -2.0f * norm;

        float nsq = norm * norm;
        nsq += __shfl_down_sync(0xffffffffu, nsq, 4, 8);
        nsq += __shfl_down_sync(0xffffffffu, nsq, 2, 8);
        nsq += __shfl_down_sync(0xffffffffu, nsq, 1, 8);
        if (c == 0) g_kc[k * 64 + sp * 2 + half] = nsq;
    }

    // PDL: results of this block are done; allow dependent grid to sync.
    cudaTriggerProgrammaticLaunchCompletion();
}

// ---------------------------------------------------------------------------
// Kernel 2: persistent-lite. Block = (1 k, 1 b), processes BOTH 256-t chunks.
// Table loaded once per block; both chunks' raw windows LDG'd into registers
// BEFORE the PDL sync (latency hidden behind stats kernel + chunk-0 compute).
// 4 warps split s 4-way (8 sp each); lane = 8 consecutive t from a 15-sample
// register window. Grid: (32 k, 16 b) = 512 blocks of 128 threads, 4/SM.
// ---------------------------------------------------------------------------
__device__ __forceinline__ unsigned long long fma2(unsigned long long a,
                                                   unsigned long long b,
                                                   unsigned long long c) {
    unsigned long long d;
    asm("fma.rn.f32x2 %0, %1, %2, %3;" : "=l"(d) : "l"(a), "l"(b), "l"(c));
    return d;
}

#define SXP_IDX(v) ((v) + ((v) >> 3))   // skewed layout: stride-8 -> stride-9

__global__ void __launch_bounds__(128, 4)
lsd_main_kernel(const float* __restrict__ x, float* __restrict__ out) {
    __shared__ float sxp[2][324];                     // raw windows, both chunks
    __shared__ __align__(16) float skq[512];          // this k's packed table
    __shared__ __align__(16) float skc[64];           // this k's ||K||^2 pairs
    __shared__ float so[4][264];                      // per-warp partial mins

    int tid = threadIdx.x;
    int w   = tid >> 5;          // warp -> sp quarter
    int l   = tid & 31;          // lane
    int k   = blockIdx.x;
    int b   = blockIdx.y;

    int cx = k >> 2;
    int m  = k & 3;

    // --- PRE-SYNC: LDG raw windows for BOTH chunks (no stats dependency) ---
    float r1buf[3];
    {
        const float* xb = x + (size_t)b * T_ * C_ + cx;
        #pragma unroll
        for (int rep = 0; rep < 3; rep++) {
            int j = tid + rep * 128;
            float v0 = 0.0f, v1 = 0.0f;
            if (j < 287) {
                v0 = xb[(size_t)j * C_];                 // chunk0: t = j (<512)
                int t1 = 256 + j;
                if (t1 < T_) v1 = xb[(size_t)t1 * C_];   // chunk1: t = 256+j
                sxp[0][SXP_IDX(j)] = v0;
            }
            r1buf[rep] = v1;
        }
    }

    // Wait for stats kernel results to be visible.
    cudaGridDependencySynchronize();

    // --- table (once per block) ---
    {
        const float4* src = (const float4*)(g_kq + (size_t)k * 512);
        ((float4*)skq)[tid] = src[tid];
        if (tid < 16) ((float4*)skc)[tid] = ((const float4*)(g_kc + (size_t)k * 64))[tid];
    }
    __syncthreads();

    float mean = g_xmean[b * C_ + cx];
    float rstd = g_xrstd[b * C_ + cx];
    float nmr  = -mean * rstd;

    const ulonglong2* kq2 = (const ulonglong2*)skq;     // idx: sp*4 + q
    const unsigned long long* kcp = (const unsigned long long*)skc;
    int base = l * 8 + m * 8;

    #pragma unroll
    for (int chunk = 0; chunk < 2; chunk++) {
        // --- per-lane register window: 15 packed {v,v}, normalized ---
        unsigned long long w2[15];
        float pn[8];
        #pragma unroll
        for (int v = 0; v < 15; v++) {
            float f = fmaf(sxp[chunk][SXP_IDX(base + v)], rstd, nmr);
            unsigned int u = __float_as_uint(f);
            w2[v] = ((unsigned long long)u << 32) | u;
        }
        #pragma unroll
        for (int j = 0; j < 8; j++) {
            float acc = 0.0f;
            #pragma unroll
            for (int i = 0; i < 8; i++) {
                float f = __uint_as_float((unsigned int)w2[j + i]);
                acc = fmaf(f, f, acc);
            }
            pn[j] = acc;   // ||p||^2 for local t = l*8 + j
        }

        float mn[8];
        #pragma unroll
        for (int j = 0; j < 8; j++) mn[j] = 3.402823466e38f;

        #pragma unroll
        for (int spq = 0; spq < 8; spq++) {
            int sp = (w << 3) + spq;
            ulonglong2 q0 = kq2[sp * 4 + 0];
            ulonglong2 q1 = kq2[sp * 4 + 1];
            ulonglong2 q2 = kq2[sp * 4 + 2];
            ulonglong2 q3 = kq2[sp * 4 + 3];
            unsigned long long c0 = kcp[sp];
            #pragma unroll
            for (int j = 0; j < 8; j++) {
                unsigned long long d = c0;
                d = fma2(w2[j + 0], q0.x, d);
                d = fma2(w2[j + 1], q0.y, d);
                d = fma2(w2[j + 2], q1.x, d);
                d = fma2(w2[j + 3], q1.y, d);
                d = fma2(w2[j + 4], q2.x, d);
                d = fma2(w2[j + 5], q2.y, d);
                d = fma2(w2[j + 6], q3.x, d);
                d = fma2(w2[j + 7], q3.y, d);
                float lo = __uint_as_float((unsigned int)d);
                float hi = __uint_as_float((unsigned int)(d >> 32));
                mn[j] = fminf(mn[j], fminf(lo, hi));
            }
        }

        // --- partial mins -> smem (conflict-free: so[w][j*33 + l]) ---
        #pragma unroll
        for (int j = 0; j < 8; j++) {
            so[w][j * 33 + l] = pn[j] + mn[j];
        }
        __syncthreads();

        // --- combine 4 warps' s-partials, store (2 t per thread) ---
        int t0 = chunk << 8;
        #pragma unroll
        for (int rep = 0; rep < 2; rep++) {
            int tt = tid + rep * 128;        // local t
            int t = t0 + tt;
            if (t < TOUT_) {
                int jj = tt & 7;
                int ll = tt >> 3;
                int idx = jj * 33 + ll;
                float v = fminf(fminf(so[0][idx], so[1][idx]),
                                fminf(so[2][idx], so[3][idx]));
                out[((size_t)b * TOUT_ + t) * KSZ_ + k] = v;
            }
        }

        if (chunk == 0) {
            // Stage chunk1 window (already in registers since pre-sync).
            #pragma unroll
            for (int rep = 0; rep < 3; rep++) {
                int j = tid + rep * 128;
                if (j < 287) sxp[1][SXP_IDX(j)] = r1buf[rep];
            }
            __syncthreads();   // covers so reuse + sxp[1] readiness
        }
    }
}

extern "C" void kernel_launch(void* const* d_in, const int* in_sizes, int n_in,
                              void* d_out, int out_size) {
    const float* x    = (const float*)d_in[0];   // (16, 512, 8)
    const float* kern = (const float*)d_in[1];   // (64, 32, 8)
    float* out = (float*)d_out;                  // (16, 481, 32)

    lsd_stats_kernel<<<192, 256>>>(x, kern);

    // PDL: main kernel may begin (raw window LDGs) while stats still runs.
    cudaLaunchAttribute attrs[1];
    attrs[0].id = cudaLaunchAttributeProgrammaticStreamSerialization;
    attrs[0].val.programmaticStreamSerializationAllowed = 1;

    cudaLaunchConfig_t cfg = {};
    cfg.gridDim  = dim3(32, 16, 1);   // (k, batch)
    cfg.blockDim = dim3(128, 1, 1);
    cfg.dynamicSmemBytes = 0;
    cfg.stream = 0;
    cfg.attrs = attrs;
    cfg.numAttrs = 1;

    cudaLaunchKernelEx(&cfg, lsd_main_kernel, x, out);
}

// round 11
// speedup vs baseline: 1.1086x; 1.1086x over previous
#include <cuda_runtime.h>
#include <cuda_bf16.h>
#include <math.h>

// Problem constants
#define B_   16
#define T_   512
#define C_   8
#define S_   64
#define KSZ_ 32
#define TOUT_ 481   // T - KSZ + 1

// Scratch (no allocations allowed in kernel_launch)
__device__ float g_xmean[B_ * C_];
__device__ float g_xrstd[B_ * C_];
// Packed kernel constants, per k (KSZ index):
//   g_kq[k*512 + sp*16 + i*2 + half] = -2 * kern_norm[s = 2*sp + half][k][i]
__device__ __align__(16) float g_kq[KSZ_ * 32 * 16];   // 16384 floats
//   g_kc[k*64 + sp*2 + half] = sum_c kern_norm[s][k][c]^2
__device__ __align__(16) float g_kc[KSZ_ * S_];        // 2048 floats

// ---------------------------------------------------------------------------
__device__ __forceinline__ void warp_red2(float& a, float& b) {
    #pragma unroll
    for (int o = 16; o > 0; o >>= 1) {
        a += __shfl_xor_sync(0xffffffffu, a, o);
        b += __shfl_xor_sync(0xffffffffu, b, o);
    }
}

// ---------------------------------------------------------------------------
// Kernel 1: stats + kernel normalization/reorder. Triggers PDL at end.
// ---------------------------------------------------------------------------
__global__ void lsd_stats_kernel(const float* __restrict__ x,
                                 const float* __restrict__ kern) {
    __shared__ float r1[8];
    __shared__ float r2[8];
    __shared__ float s_mean, s_rstd;
    int tid = threadIdx.x;
    int wid = tid >> 5;
    int lid = tid & 31;

    if (blockIdx.x < 128) {
        int b = blockIdx.x >> 3;
        int c = blockIdx.x & 7;
        const float* xp = x + (size_t)b * T_ * C_ + c;
        float v0 = xp[(size_t)tid * C_];
        float v1 = xp[(size_t)(tid + 256) * C_];
        float sum = v0 + v1;
        float sq  = v0 * v0 + v1 * v1;
        warp_red2(sum, sq);
        if (lid == 0) { r1[wid] = sum; r2[wid] = sq; }
        __syncthreads();
        if (wid == 0) {
            float a = (lid < 8) ? r1[lid] : 0.0f;
            float bq = (lid < 8) ? r2[lid] : 0.0f;
            #pragma unroll
            for (int o = 4; o > 0; o >>= 1) {
                a  += __shfl_xor_sync(0xffffffffu, a, o);
                bq += __shfl_xor_sync(0xffffffffu, bq, o);
            }
            if (lid == 0) {
                float mean = a * (1.0f / T_);
                float var  = bq * (1.0f / T_) - mean * mean;
                float std  = sqrtf(fmaxf(var, 0.0f)) + 1e-8f;
                g_xmean[b * C_ + c] = mean;
                g_xrstd[b * C_ + c] = 1.0f / std;
            }
        }
    } else {
        int s = blockIdx.x - 128;
        const float* kp = kern + (size_t)s * KSZ_ * C_;
        float v = kp[tid];
        float sum = v, sq = v * v;
        warp_red2(sum, sq);
        if (lid == 0) { r1[wid] = sum; r2[wid] = sq; }
        __syncthreads();
        if (tid == 0) {
            float a = 0.0f, bq = 0.0f;
            #pragma unroll
            for (int j = 0; j < 8; j++) { a += r1[j]; bq += r2[j]; }
            float mean = a * (1.0f / 256.0f);
            float var  = bq * (1.0f / 256.0f) - mean * mean;
            float std  = sqrtf(fmaxf(var, 0.0f)) + 1e-8f;
            s_mean = mean;
            s_rstd = 1.0f / std;
        }
        __syncthreads();

        float norm = (v - s_mean) * s_rstd;
        int k = tid >> 3;
        int c = tid & 7;
        int sp = s >> 1;
        int half = s & 1;
        g_kq[k * 512 + sp * 16 + c * 2 + half] = -2.0f * norm;

        float nsq = norm * norm;
        nsq += __shfl_down_sync(0xffffffffu, nsq, 4, 8);
        nsq += __shfl_down_sync(0xffffffffu, nsq, 2, 8);
        nsq += __shfl_down_sync(0xffffffffu, nsq, 1, 8);
        if (c == 0) g_kc[k * 64 + sp * 2 + half] = nsq;
    }

    // PDL: results of this block are done; allow dependent grid to sync.
    cudaTriggerProgrammaticLaunchCompletion();
}

// ---------------------------------------------------------------------------
// Kernel 2 (R9 math, reg-capped for single-wave residency):
// block = (1 k) x (256 t). 4 warps split s 4-way (8 sp each); each lane
// produces 8 consecutive t from a 15-sample register window. Raw window
// load happens BEFORE the PDL sync. __launch_bounds__(128,7) caps regs at
// 72 so all 1024 blocks are co-resident (7 x 148 = 1036) in one wave.
// ---------------------------------------------------------------------------
__device__ __forceinline__ unsigned long long fma2(unsigned long long a,
                                                   unsigned long long b,
                                                   unsigned long long c) {
    unsigned long long d;
    asm("fma.rn.f32x2 %0, %1, %2, %3;" : "=l"(d) : "l"(a), "l"(b), "l"(c));
    return d;
}

#define SXP_IDX(v) ((v) + ((v) >> 3))   // skewed layout: stride-8 -> stride-9

__global__ void __launch_bounds__(128, 7)
lsd_main_kernel(const float* __restrict__ x, float* __restrict__ out) {
    __shared__ float sxp[324];                        // skewed RAW window
    __shared__ __align__(16) float skq[512];          // this k's packed table
    __shared__ __align__(16) float skc[64];           // this k's ||K||^2 pairs
    __shared__ float so[4][264];                      // per-warp partial mins

    int tid = threadIdx.x;
    int w   = tid >> 5;          // warp -> sp quarter
    int l   = tid & 31;          // lane
    int k   = blockIdx.x;
    int t0  = blockIdx.y << 8;   // 0 or 256
    int b   = blockIdx.z;

    int cx = k >> 2;
    int m  = k & 3;

    // --- PRE-SYNC: stage RAW x window (no stats dependency) ---
    {
        #pragma unroll
        for (int rep = 0; rep < 3; rep++) {
            int j = tid + rep * 128;
            if (j < 287) {
                float v = 0.0f;
                int tg = t0 + j;
                if (tg < T_) v = x[((size_t)b * T_ + tg) * C_ + cx];
                sxp[SXP_IDX(j)] = v;
            }
        }
    }

    // Wait for stats kernel results to be visible.
    cudaGridDependencySynchronize();

    // --- POST-SYNC: stage this k's kernel table ---
    {
        const float4* src = (const float4*)(g_kq + (size_t)k * 512);
        ((float4*)skq)[tid] = src[tid];
        if (tid < 16) ((float4*)skc)[tid] = ((const float4*)(g_kc + (size_t)k * 64))[tid];
    }
    __syncthreads();

    float mean = g_xmean[b * C_ + cx];
    float rstd = g_xrstd[b * C_ + cx];
    float nmr  = -mean * rstd;

    // --- per-lane register window: 15 packed {v,v}, normalized on the fly ---
    int base = l * 8 + m * 8;
    unsigned long long w2[15];
    #pragma unroll
    for (int v = 0; v < 15; v++) {
        float f = fmaf(sxp[SXP_IDX(base + v)], rstd, nmr);
        unsigned int u = __float_as_uint(f);
        w2[v] = ((unsigned long long)u << 32) | u;
    }

    // --- main loop: this warp's 8 sp (16 s values) ---
    const ulonglong2* kq2 = (const ulonglong2*)skq;     // idx: sp*4 + q
    const unsigned long long* kcp = (const unsigned long long*)skc;

    float mn[8];
    #pragma unroll
    for (int j = 0; j < 8; j++) mn[j] = 3.402823466e38f;

    #pragma unroll
    for (int spq = 0; spq < 8; spq++) {
        int sp = (w << 3) + spq;
        ulonglong2 q0 = kq2[sp * 4 + 0];
        ulonglong2 q1 = kq2[sp * 4 + 1];
        ulonglong2 q2 = kq2[sp * 4 + 2];
        ulonglong2 q3 = kq2[sp * 4 + 3];
        unsigned long long c0 = kcp[sp];
        #pragma unroll
        for (int j = 0; j < 8; j++) {
            unsigned long long d = c0;
            d = fma2(w2[j + 0], q0.x, d);
            d = fma2(w2[j + 1], q0.y, d);
            d = fma2(w2[j + 2], q1.x, d);
            d = fma2(w2[j + 3], q1.y, d);
            d = fma2(w2[j + 4], q2.x, d);
            d = fma2(w2[j + 5], q2.y, d);
            d = fma2(w2[j + 6], q3.x, d);
            d = fma2(w2[j + 7], q3.y, d);
            float lo = __uint_as_float((unsigned int)d);
            float hi = __uint_as_float((unsigned int)(d >> 32));
            mn[j] = fminf(mn[j], fminf(lo, hi));
        }
    }

    // --- ||p||^2 computed AFTER the loop (w2 still live; frees 8 regs
    //     during the main loop) ---
    #pragma unroll
    for (int j = 0; j < 8; j++) {
        float acc = 0.0f;
        #pragma unroll
        for (int i = 0; i < 8; i++) {
            float f = __uint_as_float((unsigned int)w2[j + i]);
            acc = fmaf(f, f, acc);
        }
        so[w][j * 33 + l] = acc + mn[j];
    }
    __syncthreads();

    // --- combine 4 warps' s-partials, store (2 t per thread) ---
    #pragma unroll
    for (int rep = 0; rep < 2; rep++) {
        int tt = tid + rep * 128;        // local t
        int t = t0 + tt;
        if (t < TOUT_) {
            int jj = tt & 7;
            int ll = tt >> 3;
            int idx = jj * 33 + ll;
            float v = fminf(fminf(so[0][idx], so[1][idx]),
                            fminf(so[2][idx], so[3][idx]));
            out[((size_t)b * TOUT_ + t) * KSZ_ + k] = v;
        }
    }
}

extern "C" void kernel_launch(void* const* d_in, const int* in_sizes, int n_in,
                              void* d_out, int out_size) {
    const float* x    = (const float*)d_in[0];   // (16, 512, 8)
    const float* kern = (const float*)d_in[1];   // (64, 32, 8)
    float* out = (float*)d_out;                  // (16, 481, 32)

    lsd_stats_kernel<<<192, 256>>>(x, kern);

    // PDL: main kernel may begin (raw window loads) while stats still runs.
    cudaLaunchAttribute attrs[1];
    attrs[0].id = cudaLaunchAttributeProgrammaticStreamSerialization;
    attrs[0].val.programmaticStreamSerializationAllowed = 1;

    cudaLaunchConfig_t cfg = {};
    cfg.gridDim  = dim3(32, 2, 16);   // (k, t-chunks, batch)
    cfg.blockDim = dim3(128, 1, 1);
    cfg.dynamicSmemBytes = 0;
    cfg.stream = 0;
    cfg.attrs = attrs;
    cfg.numAttrs = 1;

    cudaLaunchKernelEx(&cfg, lsd_main_kernel, x, out);
}